// round 9
// baseline (speedup 1.0000x reference)
#include <cuda_runtime.h>
#include <cuda_bf16.h>

// SepConv: out[b,c,i,j] = sum_{u,v} img[b,c,i+u,j+v] * vert[b,u,i,j] * hori[b,v,i,j]
// Shapes: img[8,3,512,512], hori[8,13,500,500], vert[8,13,500,500], out[8,3,500,500]
// R8: v-split work quantum. Tile = 32x5 outputs, block (32,5,2)=320 threads.
//     z=0/z=1 twins each do ~half the 13 v-taps of every (u,c) unit (boundary
//     6+((u+c)&1) -> 253/254 taps, statically balanced), combined via one smem
//     reduction. Halved per-thread work -> makespan 10.81->11 rounds (1.8% tail
//     vs ~10% in R6). hw regs 52->28, window LDS 4->3 per unit.

#define KSZ 13
#define CC  3
#define WW  512
#define HH  512
#define WO  500
#define HO  500

#define TX  32                 // j-groups; each thread covers 4 j
#define TY  5                  // output rows per block (100 blocks exact)
#define JBLK (TX * 4)          // 128 output columns
#define TILE_ROWS (TY + KSZ - 1)   // 17 img rows
#define TILE_Q   36                // float4 per tile row (144 floats)

__global__ __launch_bounds__(TX * TY * 2, 2)
void sepconv_kernel(const float* __restrict__ img,
                    const float* __restrict__ hori,
                    const float* __restrict__ vert,
                    float* __restrict__ out) {
    __shared__ float4 s[CC][TILE_ROWS][TILE_Q];
    __shared__ float4 red[TY][TX][CC];

    const int b  = blockIdx.z;
    const int j0 = blockIdx.x * JBLK;
    const int i0 = blockIdx.y * TY;
    const int tx = threadIdx.x;
    const int ry = threadIdx.y;
    const int z  = threadIdx.z;
    const int tid = tx + TX * (ry + TY * z);
    const int NT  = TX * TY * 2;          // 320

    // ---- cooperative load of the img tile (3 channels, 17 rows, 144 cols) ----
    const int NQ = CC * TILE_ROWS * TILE_Q;   // 1836 float4
    for (int f = tid; f < NQ; f += NT) {
        int c   = f / (TILE_ROWS * TILE_Q);
        int rem = f - c * (TILE_ROWS * TILE_Q);
        int r   = rem / TILE_Q;
        int q   = rem - r * TILE_Q;
        int gx  = i0 + r;                     // i0<=495, r<=16 -> <=511 exact
        int gy  = j0 + 4 * q;
        const float* base = img + (((size_t)b * CC + c) * WW + gx) * HH;
        float4 val;
        if (gy + 3 <= HH - 1) {
            val = *(const float4*)(base + gy);
        } else {
            int y0 = gy     < HH ? gy     : HH - 1;
            int y1 = gy + 1 < HH ? gy + 1 : HH - 1;
            int y2 = gy + 2 < HH ? gy + 2 : HH - 1;
            int y3 = gy + 3 < HH ? gy + 3 : HH - 1;
            val = make_float4(base[y0], base[y1], base[y2], base[y3]);
        }
        s[c][r][q] = val;
    }
    __syncthreads();

    const int i = i0 + ry;                // always < 500 (100*5 exact)
    const int j = j0 + 4 * tx;
    const bool active = (j < HO);         // HO%4==0 -> float4 fully valid

    float4 acc[CC];
    #pragma unroll
    for (int c = 0; c < CC; c++) acc[c] = make_float4(0.f, 0.f, 0.f, 0.f);

    if (active) {
        // ---- this half's hori weights: z=0 -> v 0..6, z=1 -> v 6..12 ----
        float4 hwz[7];
        const float* hbase = hori + (((size_t)b * KSZ + (z ? 6 : 0)) * WO + i) * HO + j;
        #pragma unroll
        for (int t = 0; t < 7; t++)
            hwz[t] = *(const float4*)(hbase + (size_t)t * WO * HO);

        const float* vbase = vert + (((size_t)b * KSZ) * WO + i) * HO + j;

        if (z == 0) {
            #pragma unroll
            for (int u = 0; u < KSZ; u++) {
                float4 vw = *(const float4*)(vbase + (size_t)u * WO * HO);
                #pragma unroll
                for (int c = 0; c < CC; c++) {
                    const int par = (u + c) & 1;        // compile-time after unroll
                    const float4* rowp = &s[c][ry + u][0] + tx;
                    float4 t0 = rowp[0], t1 = rowp[1], t2 = rowp[2];
                    float w[12] = { t0.x, t0.y, t0.z, t0.w,
                                    t1.x, t1.y, t1.z, t1.w,
                                    t2.x, t2.y, t2.z, t2.w };
                    float r0 = 0.f, r1 = 0.f, r2 = 0.f, r3 = 0.f;
                    #pragma unroll
                    for (int v = 0; v < 7; v++) {
                        if (v < 6 + par) {              // static: 6 or 7 taps
                            r0 = fmaf(hwz[v].x, w[v + 0], r0);
                            r1 = fmaf(hwz[v].y, w[v + 1], r1);
                            r2 = fmaf(hwz[v].z, w[v + 2], r2);
                            r3 = fmaf(hwz[v].w, w[v + 3], r3);
                        }
                    }
                    acc[c].x = fmaf(vw.x, r0, acc[c].x);
                    acc[c].y = fmaf(vw.y, r1, acc[c].y);
                    acc[c].z = fmaf(vw.z, r2, acc[c].z);
                    acc[c].w = fmaf(vw.w, r3, acc[c].w);
                }
            }
        } else {
            #pragma unroll
            for (int u = 0; u < KSZ; u++) {
                float4 vw = *(const float4*)(vbase + (size_t)u * WO * HO);
                #pragma unroll
                for (int c = 0; c < CC; c++) {
                    const int par = (u + c) & 1;        // start tap: v = 6+par
                    const float4* rowp = &s[c][ry + u][0] + tx;
                    float4 t1 = rowp[1], t2 = rowp[2], t3 = rowp[3];
                    float w[12] = { t1.x, t1.y, t1.z, t1.w,   // cols j+4 .. j+15
                                    t2.x, t2.y, t2.z, t2.w,
                                    t3.x, t3.y, t3.z, t3.w };
                    float r0 = 0.f, r1 = 0.f, r2 = 0.f, r3 = 0.f;
                    #pragma unroll
                    for (int t = 0; t < 7; t++) {       // v = 6 + t
                        if (t >= par) {                 // static: skip v=6 when par=1
                            r0 = fmaf(hwz[t].x, w[t + 2], r0);  // w[v+r-4]
                            r1 = fmaf(hwz[t].y, w[t + 3], r1);
                            r2 = fmaf(hwz[t].z, w[t + 4], r2);
                            r3 = fmaf(hwz[t].w, w[t + 5], r3);
                        }
                    }
                    acc[c].x = fmaf(vw.x, r0, acc[c].x);
                    acc[c].y = fmaf(vw.y, r1, acc[c].y);
                    acc[c].z = fmaf(vw.z, r2, acc[c].z);
                    acc[c].w = fmaf(vw.w, r3, acc[c].w);
                }
            }
        }
    }

    // ---- combine halves: z=1 publishes, z=0 adds and stores ----
    if (z == 1 && active) {
        #pragma unroll
        for (int c = 0; c < CC; c++) red[ry][tx][c] = acc[c];
    }
    __syncthreads();
    if (z == 0 && active) {
        #pragma unroll
        for (int c = 0; c < CC; c++) {
            float4 p = red[ry][tx][c];
            float4 o = make_float4(acc[c].x + p.x, acc[c].y + p.y,
                                   acc[c].z + p.z, acc[c].w + p.w);
            float* obase = out + (((size_t)b * CC + c) * WO + i) * HO + j;
            *(float4*)obase = o;
        }
    }
}

extern "C" void kernel_launch(void* const* d_in, const int* in_sizes, int n_in,
                              void* d_out, int out_size) {
    const float* img  = (const float*)d_in[0];
    const float* hori = (const float*)d_in[1];
    const float* vert = (const float*)d_in[2];
    float* out = (float*)d_out;

    const int B = 8;
    dim3 block(TX, TY, 2);                  // 320 threads
    dim3 grid((HO + JBLK - 1) / JBLK,       // 4
              WO / TY,                      // 100 (exact)
              B);                           // 8 -> 3200 blocks
    sepconv_kernel<<<grid, block>>>(img, hori, vert, out);
}

// round 11
// speedup vs baseline: 1.7448x; 1.7448x over previous
#include <cuda_runtime.h>
#include <cuda_bf16.h>

// SepConv: out[b,c,i,j] = sum_{u,v} img[b,c,i+u,j+v] * vert[b,u,i,j] * hori[b,v,i,j]
// Shapes: img[8,3,512,512], hori[8,13,500,500], vert[8,13,500,500], out[8,3,500,500]
// Factorized: out = sum_u vert[u] * (sum_v hori[v] * img[i+u, j+v])
// R9: R1 skeleton (best: 86.8us). Prologue overlap:
//   - 13 hori LDGs + vert[0] LDG hoisted ABOVE the smem tile load (independent
//     of smem; barrier was blocking the compiler from this motion) -> weight
//     latency rides under the tile LDG->STS chain instead of after it.
//   - vert[u+1] software prefetch in the mainloop (R6-proven).
// Inner loop byte-for-byte the proven R1 codegen.

#define KSZ 13
#define CC  3
#define WW  512
#define HH  512
#define WO  500
#define HO  500

#define TX  32                 // thread-groups in j; each thread covers 4 j
#define TY  8                  // output rows per block
#define JBLK (TX * 4)          // 128 output columns per block
#define TILE_ROWS (TY + KSZ - 1)   // 20 img rows
#define TILE_Q   36                // float4 per tile row (144 floats)

__global__ __launch_bounds__(TX * TY, 2)
void sepconv_kernel(const float* __restrict__ img,
                    const float* __restrict__ hori,
                    const float* __restrict__ vert,
                    float* __restrict__ out) {
    __shared__ float4 s[CC][TILE_ROWS][TILE_Q];

    const int b  = blockIdx.z;
    const int j0 = blockIdx.x * JBLK;
    const int i0 = blockIdx.y * TY;
    const int tx = threadIdx.x, ty = threadIdx.y;
    const int tid = ty * TX + tx;

    const int i = i0 + ty;
    const int j = j0 + 4 * tx;
    const bool active = (i < WO) && (j < HO);    // HO%4==0 -> float4 valid when j<HO
    // clamped coords so edge threads issue harmless in-bounds loads
    const int ic = (i < WO) ? i : (WO - 1);
    const int jc = (j < HO) ? j : (HO - 4);

    // ---- weight loads FIRST: independent of smem, overlap the tile load ----
    float4 hw[KSZ];
    const float* hbase = hori + (((size_t)b * KSZ) * WO + ic) * HO + jc;
    #pragma unroll
    for (int v = 0; v < KSZ; v++)
        hw[v] = *(const float4*)(hbase + (size_t)v * WO * HO);

    const float* vbase = vert + (((size_t)b * KSZ) * WO + ic) * HO + jc;
    float4 vw_next = *(const float4*)(vbase);

    // ---- cooperative load of the img tile (3 channels, 20 rows, 144 cols) ----
    const int NQ = CC * TILE_ROWS * TILE_Q;   // 2160 float4
    for (int f = tid; f < NQ; f += TX * TY) {
        int c   = f / (TILE_ROWS * TILE_Q);
        int rem = f - c * (TILE_ROWS * TILE_Q);
        int r   = rem / TILE_Q;
        int q   = rem - r * TILE_Q;
        int gx  = i0 + r; if (gx > WW - 1) gx = WW - 1;   // clamped rows feed only invalid outs
        int gy  = j0 + 4 * q;
        const float* base = img + (((size_t)b * CC + c) * WW + gx) * HH;
        float4 val;
        if (gy + 3 <= HH - 1) {
            val = *(const float4*)(base + gy);
        } else {
            int y0 = gy     < HH ? gy     : HH - 1;
            int y1 = gy + 1 < HH ? gy + 1 : HH - 1;
            int y2 = gy + 2 < HH ? gy + 2 : HH - 1;
            int y3 = gy + 3 < HH ? gy + 3 : HH - 1;
            val = make_float4(base[y0], base[y1], base[y2], base[y3]);
        }
        s[c][r][q] = val;
    }
    __syncthreads();

    if (!active) return;   // no further barriers below

    float4 acc[CC];
    #pragma unroll
    for (int c = 0; c < CC; c++) acc[c] = make_float4(0.f, 0.f, 0.f, 0.f);

    #pragma unroll
    for (int u = 0; u < KSZ; u++) {
        float4 vw = vw_next;
        if (u + 1 < KSZ)
            vw_next = *(const float4*)(vbase + (size_t)(u + 1) * WO * HO);

        #pragma unroll
        for (int c = 0; c < CC; c++) {
            // 16-float register window covering columns j .. j+15 of img row i+u
            const float4* row4 = &s[c][ty + u][0] + tx;
            float w[16];
            #pragma unroll
            for (int k = 0; k < 4; k++) {
                float4 t4 = row4[k];
                w[4*k+0] = t4.x; w[4*k+1] = t4.y; w[4*k+2] = t4.z; w[4*k+3] = t4.w;
            }
            float r0 = 0.f, r1 = 0.f, r2 = 0.f, r3 = 0.f;
            #pragma unroll
            for (int v = 0; v < KSZ; v++) {
                r0 = fmaf(hw[v].x, w[v + 0], r0);
                r1 = fmaf(hw[v].y, w[v + 1], r1);
                r2 = fmaf(hw[v].z, w[v + 2], r2);
                r3 = fmaf(hw[v].w, w[v + 3], r3);
            }
            acc[c].x = fmaf(vw.x, r0, acc[c].x);
            acc[c].y = fmaf(vw.y, r1, acc[c].y);
            acc[c].z = fmaf(vw.z, r2, acc[c].z);
            acc[c].w = fmaf(vw.w, r3, acc[c].w);
        }
    }

    #pragma unroll
    for (int c = 0; c < CC; c++) {
        float* obase = out + (((size_t)b * CC + c) * WO + i) * HO + j;
        *(float4*)obase = acc[c];
    }
}

extern "C" void kernel_launch(void* const* d_in, const int* in_sizes, int n_in,
                              void* d_out, int out_size) {
    const float* img  = (const float*)d_in[0];
    const float* hori = (const float*)d_in[1];
    const float* vert = (const float*)d_in[2];
    float* out = (float*)d_out;

    const int B = 8;
    dim3 block(TX, TY);                     // 256 threads
    dim3 grid((HO + JBLK - 1) / JBLK,       // 4
              (WO + TY - 1) / TY,           // 63
              B);                           // 8 -> 2016 blocks
    sepconv_kernel<<<grid, block>>>(img, hori, vert, out);
}